// round 7
// baseline (speedup 1.0000x reference)
#include <cuda_runtime.h>
#include <cuda_fp16.h>

// Problem constants
#define T_TOTAL 4096
#define LAYERS  8
#define HIDDEN  1024
#define G4      4096
#define LETTERS 100
#define NCTA    128
#define TPB     256
#define NCELLS  (T_TOTAL * LAYERS)   // 32768
#define NLINES  8                    // barrier counter lines
#define CTAS_PER_LINE (NCTA / NLINES)   // 16
#define WSTAGE_U4 4096               // uint4 per staged layer (64KB)
#define WSMEM_BYTES (2 * WSTAGE_U4 * 16)   // 131072: double-buffered weight stage

// ---------------------------------------------------------------------------
// Device scratch
// ---------------------------------------------------------------------------
__device__ float g_gin[(size_t)T_TOTAL * LAYERS * G4];          // 512 MB input projections
__device__ __half g_w2[(size_t)LAYERS * NCTA * 32 * HIDDEN];    // 64 MB fp16 repacked W_hh
__device__ __align__(16) float g_h[2][HIDDEN];                  // ping-pong hidden state
__device__ __align__(16) float g_c[HIDDEN];                     // final cell state

struct __align__(128) CtrLine { unsigned v; unsigned pad[31]; };
__device__ CtrLine g_ctrs[NLINES];                              // spread barrier counters

__device__ __forceinline__ unsigned ld_acquire_u32(const unsigned* p) {
    unsigned v;
    asm volatile("ld.acquire.gpu.global.u32 %0, [%1];" : "=r"(v) : "l"(p) : "memory");
    return v;
}
__device__ __forceinline__ void red_release_add(unsigned* p, unsigned v) {
    asm volatile("red.release.gpu.global.add.u32 [%0], %1;" :: "l"(p), "r"(v) : "memory");
}
__device__ __forceinline__ float tanh_approx(float x) {
    float y;
    asm("tanh.approx.f32 %0, %1;" : "=f"(y) : "f"(x));
    return y;
}
__device__ __forceinline__ float sigmoid_fast(float x) {
    return 0.5f + 0.5f * tanh_approx(0.5f * x);
}
__device__ __forceinline__ void cp_async16(void* smem, const void* gmem) {
    unsigned saddr = (unsigned)__cvta_generic_to_shared(smem);
    asm volatile("cp.async.cg.shared.global [%0], [%1], 16;" :: "r"(saddr), "l"(gmem));
}
__device__ __forceinline__ void cp_async_commit() {
    asm volatile("cp.async.commit_group;" ::: "memory");
}
__device__ __forceinline__ void cp_async_wait1() {
    asm volatile("cp.async.wait_group 1;" ::: "memory");
}
__device__ __forceinline__ void dot8(float& acc, uint4 wv, float4 hA, float4 hB) {
    const __half2* hp = (const __half2*)&wv;
    float2 f0 = __half22float2(hp[0]);
    float2 f1 = __half22float2(hp[1]);
    float2 f2 = __half22float2(hp[2]);
    float2 f3 = __half22float2(hp[3]);
    acc += f0.x * hA.x + f0.y * hA.y;
    acc += f1.x * hA.z + f1.y * hA.w;
    acc += f2.x * hB.x + f2.y * hB.y;
    acc += f3.x * hB.z + f3.y * hB.w;
}

// ---------------------------------------------------------------------------
// Phase 1a: gin[cell][row] = W_ih@x_t + b_ih + b_hh; reset state/counters.
// ---------------------------------------------------------------------------
__global__ void precompute_kernel(const float* __restrict__ website,
                                  const float* __restrict__ payload,
                                  const float* __restrict__ W_ih,
                                  const float* __restrict__ b_ih,
                                  const float* __restrict__ b_hh) {
    __shared__ float Xsm[16 * LETTERS];
    const int rt = blockIdx.x;
    const int l  = blockIdx.y;
    const int t0 = blockIdx.z * 16;

    for (int idx = threadIdx.x; idx < 16 * LETTERS; idx += 128) {
        int tt = idx / LETTERS, k = idx % LETTERS;
        int t = t0 + tt;
        Xsm[idx] = (t < 2048) ? website[t * LETTERS + k]
                              : payload[(t - 2048) * LETTERS + k];
    }
    __syncthreads();

    const int row = rt * 128 + threadIdx.x;
    const float* wp = W_ih + ((size_t)l * G4 + row) * LETTERS;

    float acc[16];
#pragma unroll
    for (int tt = 0; tt < 16; tt++) acc[tt] = 0.0f;
    for (int k = 0; k < LETTERS; k++) {
        float w = __ldg(wp + k);
#pragma unroll
        for (int tt = 0; tt < 16; tt++) acc[tt] += w * Xsm[tt * LETTERS + k];
    }
    const float bias = b_ih[l * G4 + row] + b_hh[l * G4 + row];
#pragma unroll
    for (int tt = 0; tt < 16; tt++) {
        size_t idx = (((size_t)(t0 + tt)) * LAYERS + l) * G4 + row;
        g_gin[idx] = acc[tt] + bias;
    }

    if (blockIdx.x == 0 && blockIdx.y == 0 && blockIdx.z == 0) {
        for (int i = threadIdx.x; i < HIDDEN; i += 128) {
            g_h[0][i] = 0.0f;
            g_h[1][i] = 0.0f;
        }
        if (threadIdx.x < NLINES) g_ctrs[threadIdx.x].v = 0;
    }
}

// ---------------------------------------------------------------------------
// Phase 1b: repack W_hh fp32 [l][row][k] -> fp16 (R2 layout, verified).
// ---------------------------------------------------------------------------
__global__ void repack_whh_kernel(const float* __restrict__ W_hh) {
    size_t idx = (size_t)blockIdx.x * 1024 + threadIdx.x;   // over 8*4096*1024
    int k = (int)(idx & 1023);
    size_t rowl = idx >> 10;
    int row = (int)(rowl & 4095);
    int l   = (int)(rowl >> 12);
    int g = row >> 10, rem = row & 1023, bb = rem >> 3, j = rem & 7;
    int r = g * 8 + j;
    int it = k >> 8;
    int part = (k & 255) >> 7;
    int lane = (k & 127) >> 2;
    int q = part * 4 + (k & 3);
    int off = (it * 32 + lane) * 8 + q;
    g_w2[((((size_t)l * NCTA) + bb) * 32 + r) * HIDDEN + off] = __float2half(W_hh[idx]);
}

// ---------------------------------------------------------------------------
// Phase 2: persistent recurrent kernel. 128 CTAs x 256 threads.
// Warp w computes rows 4w..4w+3. Weights for cell n+1 stream GMEM->SMEM via
// cp.async while cell n waits/computes; compute reads them with LDS.128.
// ---------------------------------------------------------------------------
__global__ void __launch_bounds__(TPB, 1)
lstm_kernel(const float* __restrict__ W_lin,
            const float* __restrict__ b_lin,
            const float* __restrict__ W_out,
            const float* __restrict__ b_out,
            float* __restrict__ out) {
    __shared__ __align__(16) float h_sm[HIDDEN];
    __shared__ float g_sm[32];
    __shared__ float gin_sm[32];
    __shared__ float hn_sm[8];
    __shared__ float feat_sm[16];
    extern __shared__ __align__(16) uint4 w_sm[];   // [2][WSTAGE_U4]

    const int tid  = threadIdx.x;
    const int bb   = blockIdx.x;
    const int w    = tid >> 5;
    const int lane = tid & 31;

    // contiguous 4096-uint4 weight block for (layer l, CTA bb):
    const uint4* __restrict__ wglob = (const uint4*)g_w2;
    const size_t block_u4 = (size_t)32 * HIDDEN / 8;        // 4096
    unsigned* const my_ctr = &g_ctrs[bb & (NLINES - 1)].v;

    // ---- prologue: stage cell 0's weights into buffer 0 ----
    {
        const uint4* src = wglob + ((size_t)(0 * NCTA) + bb) * block_u4;
#pragma unroll
        for (int i = tid; i < WSTAGE_U4; i += TPB)
            cp_async16(&w_sm[i], &src[i]);
        cp_async_commit();
    }

    float c = 0.0f;   // thread tid<8 owns c[bb*8+tid]

    for (int cell = 0; cell < NCELLS; cell++) {
        const int buf = cell & 1;

        // ---- stage NEXT cell's weights (overlaps everything below) ----
        {
            const int ln = (cell + 1) & 7;
            const uint4* src = wglob + ((size_t)(ln * NCTA) + bb) * block_u4;
            uint4* dst = &w_sm[(buf ^ 1) * WSTAGE_U4];
#pragma unroll
            for (int i = tid; i < WSTAGE_U4; i += TPB)
                cp_async16(&dst[i], &src[i]);
            cp_async_commit();
        }

        // ---- gin prefetch (warp 0) ----
        if (tid < 32)
            gin_sm[tid] = __ldcs(&g_gin[(size_t)cell * G4
                                        + (tid >> 3) * HIDDEN + bb * 8 + (tid & 7)]);

        // ---- spread-counter barrier: 8 pollers, one line each ----
        if (tid < NLINES) {
            const unsigned target = (unsigned)CTAS_PER_LINE * (unsigned)cell;
            while (ld_acquire_u32(&g_ctrs[tid].v) < target) { }
        }
        __syncthreads();

        // ---- load h (4KB, coalesced) ----
        ((float4*)h_sm)[tid] = __ldcg(&((const float4*)g_h[cell & 1])[tid]);

        // ---- current cell's staged weights are complete (all but newest group) ----
        cp_async_wait1();
        __syncthreads();

        // ---- 4 row dot-products per warp; weights via conflict-free LDS.128 ----
        const uint4* wrow = &w_sm[buf * WSTAGE_U4] + w * 512;
        float acc0 = 0.f, acc1 = 0.f, acc2 = 0.f, acc3 = 0.f;
#pragma unroll
        for (int it = 0; it < 4; it++) {
            float4 hA = *(const float4*)&h_sm[it * 256 + lane * 4];
            float4 hB = *(const float4*)&h_sm[it * 256 + 128 + lane * 4];
            dot8(acc0, wrow[0 * 128 + it * 32 + lane], hA, hB);
            dot8(acc1, wrow[1 * 128 + it * 32 + lane], hA, hB);
            dot8(acc2, wrow[2 * 128 + it * 32 + lane], hA, hB);
            dot8(acc3, wrow[3 * 128 + it * 32 + lane], hA, hB);
        }
#pragma unroll
        for (int s = 16; s > 0; s >>= 1) {
            acc0 += __shfl_xor_sync(0xffffffffu, acc0, s);
            acc1 += __shfl_xor_sync(0xffffffffu, acc1, s);
            acc2 += __shfl_xor_sync(0xffffffffu, acc2, s);
            acc3 += __shfl_xor_sync(0xffffffffu, acc3, s);
        }
        if (lane == 0) {
            g_sm[w * 4 + 0] = acc0;
            g_sm[w * 4 + 1] = acc1;
            g_sm[w * 4 + 2] = acc2;
            g_sm[w * 4 + 3] = acc3;
        }
        __syncthreads();

        // ---- gates (8 threads of warp 0), coalesced h publish, arrive ----
        if (tid < 32) {
            if (tid < 8) {
                float iv = sigmoid_fast(g_sm[tid]      + gin_sm[tid]);
                float fv = sigmoid_fast(g_sm[8 + tid]  + gin_sm[8 + tid]);
                float gv = tanh_approx (g_sm[16 + tid] + gin_sm[16 + tid]);
                float ov = sigmoid_fast(g_sm[24 + tid] + gin_sm[24 + tid]);
                c = fv * c + iv * gv;
                hn_sm[tid] = ov * tanh_approx(c);
            }
            __syncwarp();
            if (tid == 0) {
                float4 a = *(const float4*)&hn_sm[0];
                float4 b = *(const float4*)&hn_sm[4];
                float4* dst = (float4*)&g_h[(cell & 1) ^ 1][bb * 8];
                dst[0] = a;
                dst[1] = b;
                red_release_add(my_ctr, 1u);   // release orders the h stores
            }
        }
    }

    // ---- publish final c, arrive once more, epilogue on CTA 0 ----
    if (tid < 8) g_c[bb * 8 + tid] = c;
    if (tid < 32) {
        __syncwarp();
        if (tid == 0) red_release_add(my_ctr, 1u);
    }

    if (bb == 0) {
        if (tid < NLINES) {
            const unsigned target = (unsigned)CTAS_PER_LINE * (unsigned)(NCELLS + 1);
            while (ld_acquire_u32(&g_ctrs[tid].v) < target) { }
        }
        __syncthreads();
        if (tid < 16) {
            const float* wl = W_lin + tid * HIDDEN;
            float a = b_lin[tid];
            for (int k = 0; k < HIDDEN; k++) a += wl[k] * __ldcg(&g_c[k]);
            feat_sm[tid] = a;
        }
        __syncthreads();
        if (tid == 0) {
            float sum = b_out[0];
#pragma unroll
            for (int k = 0; k < 16; k++) sum += W_out[k] * feat_sm[k];
            out[0] = 1.0f / (1.0f + expf(-sum));
        }
    }
}

// ---------------------------------------------------------------------------
// Harness entry. Inputs: 0 website, 1 payload, 2 W_ih, 3 W_hh, 4 b_ih,
// 5 b_hh, 6 W_lin, 7 b_lin, 8 W_out, 9 b_out
// ---------------------------------------------------------------------------
extern "C" void kernel_launch(void* const* d_in, const int* in_sizes, int n_in,
                              void* d_out, int out_size) {
    const float* website = (const float*)d_in[0];
    const float* payload = (const float*)d_in[1];
    const float* W_ih    = (const float*)d_in[2];
    const float* W_hh    = (const float*)d_in[3];
    const float* b_ih    = (const float*)d_in[4];
    const float* b_hh    = (const float*)d_in[5];
    const float* W_lin   = (const float*)d_in[6];
    const float* b_lin   = (const float*)d_in[7];
    const float* W_out   = (const float*)d_in[8];
    const float* b_out   = (const float*)d_in[9];
    float* out = (float*)d_out;

    static int attr_set = 0;
    if (!attr_set) {
        cudaFuncSetAttribute(lstm_kernel,
                             cudaFuncAttributeMaxDynamicSharedMemorySize,
                             WSMEM_BYTES);
        attr_set = 1;
    }

    dim3 grid1(32, 8, 256);
    precompute_kernel<<<grid1, 128>>>(website, payload, W_ih, b_ih, b_hh);
    repack_whh_kernel<<<(LAYERS * G4 * HIDDEN) / 1024, 1024>>>(W_hh);
    lstm_kernel<<<NCTA, TPB, WSMEM_BYTES>>>(W_lin, b_lin, W_out, b_out, out);
}

// round 8
// speedup vs baseline: 1.1356x; 1.1356x over previous
#include <cuda_runtime.h>
#include <cuda_fp16.h>

// Problem constants
#define T_TOTAL 4096
#define LAYERS  8
#define HIDDEN  1024
#define G4      4096
#define LETTERS 100
#define NCTA    128
#define TPB     256
#define NCELLS  (T_TOTAL * LAYERS)   // 32768
#define NLINES  8
#define CTAS_PER_LINE (NCTA / NLINES)   // 16
#define SMEM_LAYERS 3
#define WSMEM_BYTES (SMEM_LAYERS * 32 * HIDDEN * 2)   // 196608 (3 layers, fragment layout)

// ---------------------------------------------------------------------------
// Device scratch
// ---------------------------------------------------------------------------
__device__ float g_gin[(size_t)T_TOTAL * LAYERS * G4];          // 512 MB input projections
__device__ __half g_w2[(size_t)LAYERS * NCTA * 32 * HIDDEN];    // 64 MB fp16 W_hh, mma A-fragment layout
__device__ __align__(16) float g_h[2][HIDDEN];                  // ping-pong hidden state
__device__ __align__(16) float g_c[HIDDEN];                     // final cell state

struct __align__(128) CtrLine { unsigned v; unsigned pad[31]; };
__device__ CtrLine g_ctrs[NLINES];                              // spread barrier counters

__device__ __forceinline__ unsigned ld_acquire_u32(const unsigned* p) {
    unsigned v;
    asm volatile("ld.acquire.gpu.global.u32 %0, [%1];" : "=r"(v) : "l"(p) : "memory");
    return v;
}
__device__ __forceinline__ void red_release_add(unsigned* p, unsigned v) {
    asm volatile("red.release.gpu.global.add.u32 [%0], %1;" :: "l"(p), "r"(v) : "memory");
}
__device__ __forceinline__ float tanh_approx(float x) {
    float y;
    asm("tanh.approx.f32 %0, %1;" : "=f"(y) : "f"(x));
    return y;
}
__device__ __forceinline__ float sigmoid_fast(float x) {
    return 0.5f + 0.5f * tanh_approx(0.5f * x);
}
__device__ __forceinline__ void mma_16x8x16(float& d0, float& d1, float& d2, float& d3,
                                            uint4 a, unsigned b0, unsigned b1) {
    asm volatile(
        "mma.sync.aligned.m16n8k16.row.col.f32.f16.f16.f32 "
        "{%0,%1,%2,%3}, {%4,%5,%6,%7}, {%8,%9}, {%0,%1,%2,%3};"
        : "+f"(d0), "+f"(d1), "+f"(d2), "+f"(d3)
        : "r"(a.x), "r"(a.y), "r"(a.z), "r"(a.w), "r"(b0), "r"(b1));
}

// ---------------------------------------------------------------------------
// Phase 1a: gin[cell][row] = W_ih@x_t + b_ih + b_hh; reset state/counters.
// ---------------------------------------------------------------------------
__global__ void precompute_kernel(const float* __restrict__ website,
                                  const float* __restrict__ payload,
                                  const float* __restrict__ W_ih,
                                  const float* __restrict__ b_ih,
                                  const float* __restrict__ b_hh) {
    __shared__ float Xsm[16 * LETTERS];
    const int rt = blockIdx.x;
    const int l  = blockIdx.y;
    const int t0 = blockIdx.z * 16;

    for (int idx = threadIdx.x; idx < 16 * LETTERS; idx += 128) {
        int tt = idx / LETTERS, k = idx % LETTERS;
        int t = t0 + tt;
        Xsm[idx] = (t < 2048) ? website[t * LETTERS + k]
                              : payload[(t - 2048) * LETTERS + k];
    }
    __syncthreads();

    const int row = rt * 128 + threadIdx.x;
    const float* wp = W_ih + ((size_t)l * G4 + row) * LETTERS;

    float acc[16];
#pragma unroll
    for (int tt = 0; tt < 16; tt++) acc[tt] = 0.0f;
    for (int k = 0; k < LETTERS; k++) {
        float w = __ldg(wp + k);
#pragma unroll
        for (int tt = 0; tt < 16; tt++) acc[tt] += w * Xsm[tt * LETTERS + k];
    }
    const float bias = b_ih[l * G4 + row] + b_hh[l * G4 + row];
#pragma unroll
    for (int tt = 0; tt < 16; tt++) {
        size_t idx = (((size_t)(t0 + tt)) * LAYERS + l) * G4 + row;
        g_gin[idx] = acc[tt] + bias;
    }

    if (blockIdx.x == 0 && blockIdx.y == 0 && blockIdx.z == 0) {
        for (int i = threadIdx.x; i < HIDDEN; i += 128) {
            g_h[0][i] = 0.0f;
            g_h[1][i] = 0.0f;
        }
        if (threadIdx.x < NLINES) g_ctrs[threadIdx.x].v = 0;
    }
}

// ---------------------------------------------------------------------------
// Phase 1b: repack W_hh fp32 [l][row][k] into mma.m16n8k16 A-fragment layout.
// CTA bb, warp w owns K-chunk [w*128,(w+1)*128), rows r=0..31 (r = gate*8+j),
// tiles t = mt*8+kt (mt: 16-row tile, kt: 16-k tile). Lane = groupID*4+tg.
// uint4 comps: .x=A[g][tg*2..+1] .y=A[g+8][..] .z=A[g][tg*2+8..] .w=A[g+8][..].
// ---------------------------------------------------------------------------
__global__ void repack_whh_kernel(const float* __restrict__ W_hh) {
    size_t idx = (size_t)blockIdx.x * 1024 + threadIdx.x;   // over 8*4096*1024
    int k   = (int)(idx & 1023);
    size_t rowl = idx >> 10;
    int row = (int)(rowl & 4095);
    int l   = (int)(rowl >> 12);

    int g  = row >> 10, rem = row & 1023, bb = rem >> 3, j = rem & 7;
    int r  = g * 8 + j;                 // 0..31
    int mt = r >> 4, rr = r & 15;
    int groupID = rr & 7, rowhalf = rr >> 3;

    int w  = k >> 7, krem = k & 127;
    int kt = krem >> 4, kk = krem & 15;
    int khalf = kk >> 3, tg = (kk & 7) >> 1, oddk = kk & 1;

    int comp = khalf * 2 + rowhalf;     // 0=.x 1=.y 2=.z 3=.w
    int lane = groupID * 4 + tg;
    int t    = mt * 8 + kt;

    size_t base = ((size_t)(l * NCTA) + bb) * 32768;   // halfs per (l,bb)
    size_t dst  = base + ((size_t)(w * 16 + t) * 32 + lane) * 8 + comp * 2 + oddk;
    g_w2[dst] = __float2half(W_hh[idx]);
}

// ---------------------------------------------------------------------------
// Phase 2: persistent recurrent kernel. 128 CTAs x 256 threads.
// Warp w: all 32 rows over K-chunk [w*128,(w+1)*128) via 16 HMMA.
// Cross-warp K-reduce through psum_sm. Layers 0..2 weights resident in smem.
// ---------------------------------------------------------------------------
__global__ void __launch_bounds__(TPB, 1)
lstm_kernel(const float* __restrict__ W_lin,
            const float* __restrict__ b_lin,
            const float* __restrict__ W_out,
            const float* __restrict__ b_out,
            float* __restrict__ out) {
    __shared__ __align__(16) __half h_half[HIDDEN];   // fp16 hidden state
    __shared__ float psum_sm[32 * 9];                 // [row][warp], pitch 9
    __shared__ float g_sm[32];
    __shared__ float gin_sm[32];
    __shared__ float hn_sm[8];
    __shared__ float feat_sm[16];
    extern __shared__ __align__(16) uint4 w_sm[];     // SMEM_LAYERS * 4096 uint4

    const int tid  = threadIdx.x;
    const int bb   = blockIdx.x;
    const int w    = tid >> 5;
    const int lane = tid & 31;
    const int tg   = lane & 3;

    const uint4* __restrict__ wglob = (const uint4*)g_w2;
    const size_t block_u4 = 4096;                     // uint4 per (l,bb)
    unsigned* const my_ctr = &g_ctrs[bb & (NLINES - 1)].v;

    // ---- copy layers 0..2 of this CTA's weights into smem (once) ----
    for (int l = 0; l < SMEM_LAYERS; l++) {
        const uint4* s = wglob + ((size_t)(l * NCTA) + bb) * block_u4;
#pragma unroll
        for (int i = tid; i < 4096; i += TPB)
            w_sm[l * 4096 + i] = __ldg(&s[i]);
    }
    __syncthreads();

    float c = 0.0f;   // thread tid<8 owns c[bb*8+tid]

    for (int cell = 0; cell < NCELLS; cell++) {
        const int l = cell & 7;
        uint4 wreg[16];

        // ---- weight fragments into regs BEFORE the barrier (overlap wait) ----
        if (l < SMEM_LAYERS) {
            const uint4* wrow = w_sm + l * 4096 + w * 512;
#pragma unroll
            for (int t = 0; t < 16; t++)
                wreg[t] = wrow[t * 32 + lane];
        } else {
            const uint4* wrow = wglob + ((size_t)(l * NCTA) + bb) * block_u4 + w * 512;
#pragma unroll
            for (int t = 0; t < 16; t++)
                wreg[t] = __ldg(&wrow[t * 32 + lane]);
        }

        // ---- gin prefetch (warp 0) ----
        if (tid < 32)
            gin_sm[tid] = __ldcs(&g_gin[(size_t)cell * G4
                                        + (tid >> 3) * HIDDEN + bb * 8 + (tid & 7)]);

        // ---- spread-counter barrier ----
        if (tid < NLINES) {
            const unsigned target = (unsigned)CTAS_PER_LINE * (unsigned)cell;
            while (ld_acquire_u32(&g_ctrs[tid].v) < target) { }
        }
        __syncthreads();

        // ---- load h, convert to fp16 into smem ----
        {
            float4 hv = __ldcg(&((const float4*)g_h[cell & 1])[tid]);
            __half2 h01 = __floats2half2_rn(hv.x, hv.y);
            __half2 h23 = __floats2half2_rn(hv.z, hv.w);
            unsigned* dst = (unsigned*)&h_half[tid * 4];
            dst[0] = *(unsigned*)&h01;
            dst[1] = *(unsigned*)&h23;
        }
        __syncthreads();

        // ---- 16 HMMA per warp: rows 0..31 x K-chunk 128 ----
        float d0[4] = {0.f, 0.f, 0.f, 0.f};   // m-tile 0 (rows 0..15)
        float d1[4] = {0.f, 0.f, 0.f, 0.f};   // m-tile 1 (rows 16..31)
        const unsigned* hb = (const unsigned*)h_half;
#pragma unroll
        for (int kt = 0; kt < 8; kt++) {
            const int kbase = w * 128 + kt * 16;
            unsigned b0 = hb[(kbase >> 1) + tg];        // h[kbase+tg*2 .. +1]
            unsigned b1 = hb[(kbase >> 1) + 4 + tg];    // h[kbase+tg*2+8 .. +9]
            mma_16x8x16(d0[0], d0[1], d0[2], d0[3], wreg[kt], b0, b1);
            mma_16x8x16(d1[0], d1[1], d1[2], d1[3], wreg[8 + kt], b0, b1);
        }

        // ---- write col-0 partials: lanes with tg==0 hold D[row][0] ----
        if (tg == 0) {
            const int gID = lane >> 2;
            psum_sm[(gID) * 9 + w]      = d0[0];
            psum_sm[(gID + 8) * 9 + w]  = d0[2];
            psum_sm[(gID + 16) * 9 + w] = d1[0];
            psum_sm[(gID + 24) * 9 + w] = d1[2];
        }
        __syncthreads();

        // ---- K-reduce over 8 warps (warp 0, 32 threads) + gates ----
        if (tid < 32) {
            const float* pr = &psum_sm[tid * 9];
            float s = ((pr[0] + pr[1]) + (pr[2] + pr[3]))
                    + ((pr[4] + pr[5]) + (pr[6] + pr[7]));
            g_sm[tid] = s;
            __syncwarp();
            if (tid < 8) {
                float iv = sigmoid_fast(g_sm[tid]      + gin_sm[tid]);
                float fv = sigmoid_fast(g_sm[8 + tid]  + gin_sm[8 + tid]);
                float gv = tanh_approx (g_sm[16 + tid] + gin_sm[16 + tid]);
                float ov = sigmoid_fast(g_sm[24 + tid] + gin_sm[24 + tid]);
                c = fv * c + iv * gv;
                hn_sm[tid] = ov * tanh_approx(c);
            }
            __syncwarp();
            if (tid == 0) {
                float4 a = *(const float4*)&hn_sm[0];
                float4 b = *(const float4*)&hn_sm[4];
                float4* dst = (float4*)&g_h[(cell & 1) ^ 1][bb * 8];
                dst[0] = a;
                dst[1] = b;
                red_release_add(my_ctr, 1u);   // release orders the h stores
            }
        }
    }

    // ---- publish final c, arrive once more, epilogue on CTA 0 ----
    if (tid < 8) g_c[bb * 8 + tid] = c;
    if (tid < 32) {
        __syncwarp();
        if (tid == 0) red_release_add(my_ctr, 1u);
    }

    if (bb == 0) {
        if (tid < NLINES) {
            const unsigned target = (unsigned)CTAS_PER_LINE * (unsigned)(NCELLS + 1);
            while (ld_acquire_u32(&g_ctrs[tid].v) < target) { }
        }
        __syncthreads();
        if (tid < 16) {
            const float* wl = W_lin + tid * HIDDEN;
            float a = b_lin[tid];
            for (int k = 0; k < HIDDEN; k++) a += wl[k] * __ldcg(&g_c[k]);
            feat_sm[tid] = a;
        }
        __syncthreads();
        if (tid == 0) {
            float sum = b_out[0];
#pragma unroll
            for (int k = 0; k < 16; k++) sum += W_out[k] * feat_sm[k];
            out[0] = 1.0f / (1.0f + expf(-sum));
        }
    }
}

// ---------------------------------------------------------------------------
// Harness entry. Inputs: 0 website, 1 payload, 2 W_ih, 3 W_hh, 4 b_ih,
// 5 b_hh, 6 W_lin, 7 b_lin, 8 W_out, 9 b_out
// ---------------------------------------------------------------------------
extern "C" void kernel_launch(void* const* d_in, const int* in_sizes, int n_in,
                              void* d_out, int out_size) {
    const float* website = (const float*)d_in[0];
    const float* payload = (const float*)d_in[1];
    const float* W_ih    = (const float*)d_in[2];
    const float* W_hh    = (const float*)d_in[3];
    const float* b_ih    = (const float*)d_in[4];
    const float* b_hh    = (const float*)d_in[5];
    const float* W_lin   = (const float*)d_in[6];
    const float* b_lin   = (const float*)d_in[7];
    const float* W_out   = (const float*)d_in[8];
    const float* b_out   = (const float*)d_in[9];
    float* out = (float*)d_out;

    static int attr_set = 0;
    if (!attr_set) {
        cudaFuncSetAttribute(lstm_kernel,
                             cudaFuncAttributeMaxDynamicSharedMemorySize,
                             WSMEM_BYTES);
        attr_set = 1;
    }

    dim3 grid1(32, 8, 256);
    precompute_kernel<<<grid1, 128>>>(website, payload, W_ih, b_ih, b_hh);
    repack_whh_kernel<<<(LAYERS * G4 * HIDDEN) / 1024, 1024>>>(W_hh);
    lstm_kernel<<<NCTA, TPB, WSMEM_BYTES>>>(W_lin, b_lin, W_out, b_out, out);
}